// round 4
// baseline (speedup 1.0000x reference)
#include <cuda_runtime.h>

#define NB 16
#define NS 4096
#define NE 8
#define NTOK (NB*NS)
#define TQ 512
#define ATTN_THREADS 64

// scratch (device globals: no allocation allowed)
__device__ float g_qrow[NTOK*NE];      // [b][s][w]  row-major features
__device__ float g_qcol[NB*NE*NS];     // [b][w][t]  transposed for packed loads
__device__ float g_att[NTOK*NE];       // attention output [b][s][e]

typedef unsigned long long u64;

__device__ __forceinline__ u64 pk2(float lo, float hi){u64 r; asm("mov.b64 %0,{%1,%2};":"=l"(r):"f"(lo),"f"(hi)); return r;}
__device__ __forceinline__ float2 upk2(u64 v){float2 f; asm("mov.b64 {%0,%1},%2;":"=f"(f.x),"=f"(f.y):"l"(v)); return f;}
__device__ __forceinline__ u64 fma2(u64 a,u64 b,u64 c){u64 d; asm("fma.rn.f32x2 %0,%1,%2,%3;":"=l"(d):"l"(a),"l"(b),"l"(c)); return d;}
__device__ __forceinline__ u64 mul2(u64 a,u64 b){u64 d; asm("mul.rn.f32x2 %0,%1,%2;":"=l"(d):"l"(a),"l"(b)); return d;}
__device__ __forceinline__ u64 add2(u64 a,u64 b){u64 d; asm("add.rn.f32x2 %0,%1,%2;":"=l"(d):"l"(a),"l"(b)); return d;}
__device__ __forceinline__ float ex2f(float x){float r; asm("ex2.approx.ftz.f32 %0,%1;":"=f"(r):"f"(x)); return r;}

// ---------------------------------------------------------------------------
// Kernel 1: quantum features.  q[w] = prefix products of cos(x+theta).
//   (CNOT-ring inverse image: q[0] = c1*...*c7, q[w>=1] = c0*...*cw)
// ---------------------------------------------------------------------------
__global__ void feat_kernel(const float* __restrict__ x, const float* __restrict__ theta)
{
    int tok = blockIdx.x*blockDim.x + threadIdx.x;
    float th[8];
    #pragma unroll
    for(int w=0;w<8;w++) th[w] = __ldg(&theta[w]);
    float4 x0 = *(const float4*)&x[tok*8];
    float4 x1 = *(const float4*)&x[tok*8+4];
    float c[8];
    c[0]=__cosf(x0.x+th[0]); c[1]=__cosf(x0.y+th[1]); c[2]=__cosf(x0.z+th[2]); c[3]=__cosf(x0.w+th[3]);
    c[4]=__cosf(x1.x+th[4]); c[5]=__cosf(x1.y+th[5]); c[6]=__cosf(x1.z+th[6]); c[7]=__cosf(x1.w+th[7]);
    float q[8];
    float p = c[0];
    #pragma unroll
    for(int w=1;w<8;w++){ p *= c[w]; q[w] = p; }
    float s = c[1];
    #pragma unroll
    for(int w=2;w<8;w++) s *= c[w];
    q[0] = s;
    *(float4*)&g_qrow[tok*8]   = make_float4(q[0],q[1],q[2],q[3]);
    *(float4*)&g_qrow[tok*8+4] = make_float4(q[4],q[5],q[6],q[7]);
    int b = tok >> 12, t = tok & (NS-1);
    #pragma unroll
    for(int w=0;w<8;w++) g_qcol[(b*8+w)*NS + t] = q[w];
}

// ---------------------------------------------------------------------------
// Kernel 2: streaming softmax attention.
//   score*log2(e) = (qs_scaled . qt), p = ex2(.) on the MUFU pipe.
//   |score| <= 8/sqrt(2) => no max-subtraction needed.
//   TQ=512 (16KB smem) -> ~10 CTAs/SM -> ~5 warps/SMSP for latency hiding.
// ---------------------------------------------------------------------------
__global__ void __launch_bounds__(ATTN_THREADS) attn_kernel()
{
    __shared__ __align__(16) float sq[8*TQ];   // [w][t] chunk, 16 KB
    const int b   = blockIdx.y;
    const int row = blockIdx.x*ATTN_THREADS + threadIdx.x;
    const float SC = 1.02013946f;              // log2(e)/sqrt(2)

    u64 qs[8];
    #pragma unroll
    for(int w=0;w<8;w++){ float v = g_qrow[(b*NS+row)*8+w]*SC; qs[w]=pk2(v,v); }
    u64 acc[8];
    #pragma unroll
    for(int w=0;w<8;w++) acc[w]=pk2(0.f,0.f);
    u64 den0 = pk2(0.f,0.f), den1 = pk2(0.f,0.f);
    const float* qc = &g_qcol[b*8*NS];

    for(int ch=0; ch<NS/TQ; ch++){
        // cooperative chunk load, float4
        #pragma unroll
        for(int i=threadIdx.x; i<8*TQ/4; i+=ATTN_THREADS){
            int w = i >> 7, t4 = i & 127;      // TQ/4 == 128
            ((float4*)sq)[(w<<7)+t4] = *(const float4*)&qc[w*NS + ch*TQ + (t4<<2)];
        }
        __syncthreads();
        #pragma unroll 4
        for(int t4=0; t4<TQ/4; t4++){
            u64 qlo[8], qhi[8];
            #pragma unroll
            for(int w=0;w<8;w++){
                ulonglong2 v = *(const ulonglong2*)&sq[w*TQ + (t4<<2)];
                qlo[w]=v.x; qhi[w]=v.y;
            }
            u64 u0 = mul2(qs[0],qlo[0]);
            u64 u1 = mul2(qs[0],qhi[0]);
            #pragma unroll
            for(int w=1;w<8;w++){
                u0 = fma2(qs[w],qlo[w],u0);
                u1 = fma2(qs[w],qhi[w],u1);
            }
            float2 a = upk2(u0), c = upk2(u1);
            u64 P0 = pk2(ex2f(a.x), ex2f(a.y));   // MUFU pipe
            u64 P1 = pk2(ex2f(c.x), ex2f(c.y));
            den0 = add2(den0,P0);
            den1 = add2(den1,P1);
            #pragma unroll
            for(int w=0;w<8;w++){
                acc[w] = fma2(P0,qlo[w],acc[w]);
                acc[w] = fma2(P1,qhi[w],acc[w]);
            }
        }
        __syncthreads();
    }

    float2 da = upk2(den0), db = upk2(den1);
    float inv = 1.0f/((da.x + da.y) + (db.x + db.y));
    float o[8];
    #pragma unroll
    for(int w=0;w<8;w++){ float2 a = upk2(acc[w]); o[w]=(a.x+a.y)*inv; }
    *(float4*)&g_att[(b*NS+row)*8]   = make_float4(o[0],o[1],o[2],o[3]);
    *(float4*)&g_att[(b*NS+row)*8+4] = make_float4(o[4],o[5],o[6],o[7]);
}

// ---------------------------------------------------------------------------
// Kernel 3: swapaxes(1,2).reshape scramble + out @ W^T + b.
//   final[b,i,e'] = b[e'] + sum_j att[b, 8*(i%512)+j, i>>9] * W[e',j]
// ---------------------------------------------------------------------------
__global__ void epi_kernel(const float* __restrict__ W, const float* __restrict__ bias,
                           float* __restrict__ out)
{
    int idx = blockIdx.x*blockDim.x + threadIdx.x;   // b*NS + i
    int i  = idx & (NS-1);
    int b  = idx >> 12;
    int e  = i >> 9;
    int s0 = (i & 511) << 3;
    const float* g = &g_att[(b*NS + s0)*8 + e];
    float y[8];
    #pragma unroll
    for(int j=0;j<8;j++) y[j] = g[j*8];
    float r[8];
    #pragma unroll
    for(int ep=0;ep<8;ep++){
        float a = __ldg(&bias[ep]);
        #pragma unroll
        for(int j=0;j<8;j++) a = fmaf(y[j], __ldg(&W[ep*8+j]), a);
        r[ep]=a;
    }
    *(float4*)&out[idx*8]   = make_float4(r[0],r[1],r[2],r[3]);
    *(float4*)&out[idx*8+4] = make_float4(r[4],r[5],r[6],r[7]);
}

extern "C" void kernel_launch(void* const* d_in, const int* in_sizes, int n_in,
                              void* d_out, int out_size)
{
    const float* x     = (const float*)d_in[0];
    const float* theta = (const float*)d_in[1];
    const float* w     = (const float*)d_in[2];
    const float* bias  = (const float*)d_in[3];
    float* out = (float*)d_out;

    feat_kernel<<<NTOK/256, 256>>>(x, theta);
    dim3 g(NS/ATTN_THREADS, NB);
    attn_kernel<<<g, ATTN_THREADS>>>();
    epi_kernel<<<NTOK/256, 256>>>(w, bias, out);
}

// round 5
// speedup vs baseline: 2.9196x; 2.9196x over previous
#include <cuda_runtime.h>

#define NB 16
#define NS 4096
#define NTOK (NB*NS)
#define CHUNK 512
#define SQS 520            // padded smem row stride (words): w*520 mod 32 = 8w

// scratch (device globals: no allocation allowed)
__device__ float g_qrow[NTOK*8];     // tf32(q * log2e/sqrt2)  [b][s][w]  (Q operand)
__device__ float g_qcol[NB*8*NS];    // tf32(q)                [b][w][t]  (K and V operand)
__device__ float g_att[NTOK*8];      // attention output

typedef unsigned int u32;

__device__ __forceinline__ float ex2f(float x){float r; asm("ex2.approx.ftz.f32 %0,%1;":"=f"(r):"f"(x)); return r;}
__device__ __forceinline__ float tf32r(float x){u32 r; asm("cvt.rna.tf32.f32 %0,%1;":"=r"(r):"f"(x)); return __uint_as_float(r);}
// pack: result.lo = lo, result.hi = hi  (cvt.bf16x2 d,A,B -> d.hi=A, d.lo=B)
__device__ __forceinline__ u32 pkbf(float hi, float lo){u32 r; asm("cvt.rn.bf16x2.f32 %0,%1,%2;":"=r"(r):"f"(hi),"f"(lo)); return r;}

__device__ __forceinline__ void mma_tf32(float* d, const u32* a, u32 b0, u32 b1){
    asm volatile("mma.sync.aligned.m16n8k8.row.col.f32.tf32.tf32.f32 "
        "{%0,%1,%2,%3},{%4,%5,%6,%7},{%8,%9},{%10,%11,%12,%13};"
        : "=f"(d[0]),"=f"(d[1]),"=f"(d[2]),"=f"(d[3])
        : "r"(a[0]),"r"(a[1]),"r"(a[2]),"r"(a[3]), "r"(b0),"r"(b1),
          "f"(0.f),"f"(0.f),"f"(0.f),"f"(0.f));
}
__device__ __forceinline__ void mma_bf16(float* d, const u32* a, u32 b0, u32 b1){
    asm volatile("mma.sync.aligned.m16n8k16.row.col.f32.bf16.bf16.f32 "
        "{%0,%1,%2,%3},{%4,%5,%6,%7},{%8,%9},{%0,%1,%2,%3};"
        : "+f"(d[0]),"+f"(d[1]),"+f"(d[2]),"+f"(d[3])
        : "r"(a[0]),"r"(a[1]),"r"(a[2]),"r"(a[3]), "r"(b0),"r"(b1));
}

// ---------------------------------------------------------------------------
// Kernel 1: quantum features (prefix cosine products), tf32-rounded outputs.
// ---------------------------------------------------------------------------
__global__ void feat_kernel(const float* __restrict__ x, const float* __restrict__ theta)
{
    int tok = blockIdx.x*blockDim.x + threadIdx.x;
    float th[8];
    #pragma unroll
    for(int w=0;w<8;w++) th[w] = __ldg(&theta[w]);
    float4 x0 = *(const float4*)&x[tok*8];
    float4 x1 = *(const float4*)&x[tok*8+4];
    float c[8];
    c[0]=__cosf(x0.x+th[0]); c[1]=__cosf(x0.y+th[1]); c[2]=__cosf(x0.z+th[2]); c[3]=__cosf(x0.w+th[3]);
    c[4]=__cosf(x1.x+th[4]); c[5]=__cosf(x1.y+th[5]); c[6]=__cosf(x1.z+th[6]); c[7]=__cosf(x1.w+th[7]);
    float q[8];
    float p = c[0];
    #pragma unroll
    for(int w=1;w<8;w++){ p *= c[w]; q[w] = p; }
    float s = c[1];
    #pragma unroll
    for(int w=2;w<8;w++) s *= c[w];
    q[0] = s;                                   // CNOT-ring inverse image
    const float SC = 1.02013946f;               // log2(e)/sqrt(2)
    float qs[8];
    #pragma unroll
    for(int w=0;w<8;w++){ qs[w]=tf32r(q[w]*SC); q[w]=tf32r(q[w]); }
    *(float4*)&g_qrow[tok*8]   = make_float4(qs[0],qs[1],qs[2],qs[3]);
    *(float4*)&g_qrow[tok*8+4] = make_float4(qs[4],qs[5],qs[6],qs[7]);
    int b = tok >> 12, t = tok & (NS-1);
    #pragma unroll
    for(int w=0;w<8;w++) g_qcol[(b*8+w)*NS + t] = q[w];
}

// ---------------------------------------------------------------------------
// Kernel 2: flash attention via warp mma.sync.
//   Warp owns 16 s-rows. Per 16-t subtile:
//     2x mma.m16n8k8.tf32  -> S(16x16) in D-regs
//     8x ex2                -> P (f32), den accumulated in f32
//     4x cvt.bf16x2         -> P as bf16 A-frag (layout-compatible)
//     2x mma.m16n8k16.bf16  -> O += P*(Vhi) + P*(Vlo)
//   Scores bounded => no online max.
// ---------------------------------------------------------------------------
__global__ void __launch_bounds__(128) attn_kernel()
{
    __shared__ __align__(16) float sq[8*SQS];    // K/V chunk [w][t], padded
    const int b    = blockIdx.y;
    const int tid  = threadIdx.x;
    const int warp = tid >> 5, lane = tid & 31;
    const int g    = lane >> 2, c = lane & 3;    // groupID, threadID-in-group
    const int row0 = blockIdx.x*64 + warp*16;

    // Q fragment (held whole kernel)
    const float* qr = &g_qrow[(b*NS+row0)*8];
    u32 qa[4];
    qa[0] = __float_as_uint(qr[ g     *8 + c  ]);
    qa[1] = __float_as_uint(qr[(g+8)  *8 + c  ]);
    qa[2] = __float_as_uint(qr[ g     *8 + c+4]);
    qa[3] = __float_as_uint(qr[(g+8)  *8 + c+4]);

    float num[4] = {0.f,0.f,0.f,0.f};
    float denl = 0.f, denh = 0.f;
    const float* qc = &g_qcol[b*8*NS];

    for(int ch=0; ch<NS/CHUNK; ch++){
        __syncthreads();
        #pragma unroll
        for(int k=0;k<8;k++){
            int i = tid + k*128;
            int w = i >> 7, t4 = i & 127;        // CHUNK/4 == 128
            *(float4*)&sq[w*SQS + (t4<<2)] = *(const float4*)&qc[w*NS + ch*CHUNK + (t4<<2)];
        }
        __syncthreads();

        for(int sub=0; sub<CHUNK/16; sub++){
            const int tb = sub*16;
            // K fragments (B of tf32 mma): b0:(k=c,n=tb+g), b1:(k=c+4,n=tb+g)
            u32 kb00 = __float_as_uint(sq[ c   *SQS + tb + g    ]);
            u32 kb01 = __float_as_uint(sq[(c+4)*SQS + tb + g    ]);
            u32 kb10 = __float_as_uint(sq[ c   *SQS + tb + 8 + g]);
            u32 kb11 = __float_as_uint(sq[(c+4)*SQS + tb + 8 + g]);
            float dl[4], dr[4];
            mma_tf32(dl, qa, kb00, kb01);        // S cols tb..tb+7
            mma_tf32(dr, qa, kb10, kb11);        // S cols tb+8..tb+15
            // exp2 (scores pre-scaled by log2e)
            dl[0]=ex2f(dl[0]); dl[1]=ex2f(dl[1]); dl[2]=ex2f(dl[2]); dl[3]=ex2f(dl[3]);
            dr[0]=ex2f(dr[0]); dr[1]=ex2f(dr[1]); dr[2]=ex2f(dr[2]); dr[3]=ex2f(dr[3]);
            denl += dl[0]+dl[1]+dr[0]+dr[1];     // row g
            denh += dl[2]+dl[3]+dr[2]+dr[3];     // row g+8
            // P as bf16 A-frag
            u32 pa[4];
            pa[0]=pkbf(dl[1],dl[0]); pa[1]=pkbf(dl[3],dl[2]);
            pa[2]=pkbf(dr[1],dr[0]); pa[3]=pkbf(dr[3],dr[2]);
            // V fragments (B of bf16 mma), hi/lo split. V[t][e]: e=g, k=t-tb
            float2 v0 = *(const float2*)&sq[g*SQS + tb + 2*c    ];   // k=2c,2c+1
            float2 v1 = *(const float2*)&sq[g*SQS + tb + 2*c + 8];   // k=2c+8,2c+9
            u32 vh0 = pkbf(v0.y, v0.x);
            u32 vh1 = pkbf(v1.y, v1.x);
            float h0x = __uint_as_float(vh0<<16), h0y = __uint_as_float(vh0 & 0xffff0000u);
            float h1x = __uint_as_float(vh1<<16), h1y = __uint_as_float(vh1 & 0xffff0000u);
            u32 vl0 = pkbf(v0.y-h0y, v0.x-h0x);
            u32 vl1 = pkbf(v1.y-h1y, v1.x-h1x);
            mma_bf16(num, pa, vh0, vh1);
            mma_bf16(num, pa, vl0, vl1);
        }
    }

    // reduce den across the 4 lanes sharing a row (tig = 0..3)
    denl += __shfl_xor_sync(0xffffffffu, denl, 1);
    denl += __shfl_xor_sync(0xffffffffu, denl, 2);
    denh += __shfl_xor_sync(0xffffffffu, denh, 1);
    denh += __shfl_xor_sync(0xffffffffu, denh, 2);
    float invl = 1.0f/denl, invh = 1.0f/denh;

    float* o1 = &g_att[(b*NS + row0 + g    )*8 + 2*c];
    float* o2 = &g_att[(b*NS + row0 + 8 + g)*8 + 2*c];
    *(float2*)o1 = make_float2(num[0]*invl, num[1]*invl);
    *(float2*)o2 = make_float2(num[2]*invh, num[3]*invh);
}

// ---------------------------------------------------------------------------
// Kernel 3: swapaxes(1,2).reshape scramble + out @ W^T + b.
// ---------------------------------------------------------------------------
__global__ void epi_kernel(const float* __restrict__ W, const float* __restrict__ bias,
                           float* __restrict__ out)
{
    int idx = blockIdx.x*blockDim.x + threadIdx.x;   // b*NS + i
    int i  = idx & (NS-1);
    int b  = idx >> 12;
    int e  = i >> 9;
    int s0 = (i & 511) << 3;
    const float* gp = &g_att[(b*NS + s0)*8 + e];
    float y[8];
    #pragma unroll
    for(int j=0;j<8;j++) y[j] = gp[j*8];
    float r[8];
    #pragma unroll
    for(int ep=0;ep<8;ep++){
        float a = __ldg(&bias[ep]);
        #pragma unroll
        for(int j=0;j<8;j++) a = fmaf(y[j], __ldg(&W[ep*8+j]), a);
        r[ep]=a;
    }
    *(float4*)&out[idx*8]   = make_float4(r[0],r[1],r[2],r[3]);
    *(float4*)&out[idx*8+4] = make_float4(r[4],r[5],r[6],r[7]);
}

extern "C" void kernel_launch(void* const* d_in, const int* in_sizes, int n_in,
                              void* d_out, int out_size)
{
    const float* x     = (const float*)d_in[0];
    const float* theta = (const float*)d_in[1];
    const float* w     = (const float*)d_in[2];
    const float* bias  = (const float*)d_in[3];
    float* out = (float*)d_out;

    feat_kernel<<<NTOK/256, 256>>>(x, theta);
    dim3 g(NS/64, NB);
    attn_kernel<<<g, 128>>>();
    epi_kernel<<<NTOK/256, 256>>>(w, bias, out);
}

// round 6
// speedup vs baseline: 3.0764x; 1.0537x over previous
#include <cuda_runtime.h>

#define NB 16
#define NS 4096
#define NTOK (NB*NS)
#define CHUNK 256
#define KS 264             // padded f32 stride for K rows
#define VS 132             // padded u32 stride for V rows (bf16x2)
#define NCH (NS/CHUNK)

// scratch (device globals: no allocation allowed)
__device__ float g_qrow[NTOK*8];            // tf32(q*log2e/sqrt2) [b][s][w] (Q operand)
__device__ float g_qcol[NB*8*NS];           // tf32(q)             [b][w][t] (K operand)
__device__ unsigned short g_vhi[NB*8*NS];   // bf16 hi of q        [b][w][t] (V operand)
__device__ unsigned short g_vlo[NB*8*NS];   // bf16 lo residual
__device__ float g_att[NTOK*8];             // attention output

typedef unsigned int u32;

__device__ __forceinline__ float ex2f(float x){float r; asm("ex2.approx.ftz.f32 %0,%1;":"=f"(r):"f"(x)); return r;}
__device__ __forceinline__ float tf32r(float x){u32 r; asm("cvt.rna.tf32.f32 %0,%1;":"=r"(r):"f"(x)); return __uint_as_float(r);}
// pack: result.lo = lo, result.hi = hi
__device__ __forceinline__ u32 pkbf(float hi, float lo){u32 r; asm("cvt.rn.bf16x2.f32 %0,%1,%2;":"=r"(r):"f"(hi),"f"(lo)); return r;}
__device__ __forceinline__ void cpa16(u32 dst, const void* src){
    asm volatile("cp.async.cg.shared.global [%0], [%1], 16;"::"r"(dst),"l"(src));
}
__device__ __forceinline__ void cpa_commit(){ asm volatile("cp.async.commit_group;"); }
__device__ __forceinline__ void cpa_wait1(){ asm volatile("cp.async.wait_group 1;"); }

__device__ __forceinline__ void mma_tf32(float* d, const u32* a, u32 b0, u32 b1){
    asm volatile("mma.sync.aligned.m16n8k8.row.col.f32.tf32.tf32.f32 "
        "{%0,%1,%2,%3},{%4,%5,%6,%7},{%8,%9},{%10,%11,%12,%13};"
        : "=f"(d[0]),"=f"(d[1]),"=f"(d[2]),"=f"(d[3])
        : "r"(a[0]),"r"(a[1]),"r"(a[2]),"r"(a[3]), "r"(b0),"r"(b1),
          "f"(0.f),"f"(0.f),"f"(0.f),"f"(0.f));
}
__device__ __forceinline__ void mma_bf16(float* d, const u32* a, u32 b0, u32 b1){
    asm volatile("mma.sync.aligned.m16n8k16.row.col.f32.bf16.bf16.f32 "
        "{%0,%1,%2,%3},{%4,%5,%6,%7},{%8,%9},{%0,%1,%2,%3};"
        : "+f"(d[0]),"+f"(d[1]),"+f"(d[2]),"+f"(d[3])
        : "r"(a[0]),"r"(a[1]),"r"(a[2]),"r"(a[3]), "r"(b0),"r"(b1));
}

// ---------------------------------------------------------------------------
// Kernel 1: quantum features (prefix cosine products).
//   Emits: Q (tf32, pre-scaled), K (tf32), V as bf16 hi/lo split.
// ---------------------------------------------------------------------------
__global__ void feat_kernel(const float* __restrict__ x, const float* __restrict__ theta)
{
    int tok = blockIdx.x*blockDim.x + threadIdx.x;
    float th[8];
    #pragma unroll
    for(int w=0;w<8;w++) th[w] = __ldg(&theta[w]);
    float4 x0 = *(const float4*)&x[tok*8];
    float4 x1 = *(const float4*)&x[tok*8+4];
    float c[8];
    c[0]=__cosf(x0.x+th[0]); c[1]=__cosf(x0.y+th[1]); c[2]=__cosf(x0.z+th[2]); c[3]=__cosf(x0.w+th[3]);
    c[4]=__cosf(x1.x+th[4]); c[5]=__cosf(x1.y+th[5]); c[6]=__cosf(x1.z+th[6]); c[7]=__cosf(x1.w+th[7]);
    float q[8];
    float p = c[0];
    #pragma unroll
    for(int w=1;w<8;w++){ p *= c[w]; q[w] = p; }
    float s = c[1];
    #pragma unroll
    for(int w=2;w<8;w++) s *= c[w];
    q[0] = s;                                   // CNOT-ring inverse image
    const float SC = 1.02013946f;               // log2(e)/sqrt(2)
    float qs[8];
    #pragma unroll
    for(int w=0;w<8;w++) qs[w]=tf32r(q[w]*SC);
    *(float4*)&g_qrow[tok*8]   = make_float4(qs[0],qs[1],qs[2],qs[3]);
    *(float4*)&g_qrow[tok*8+4] = make_float4(qs[4],qs[5],qs[6],qs[7]);
    int b = tok >> 12, t = tok & (NS-1);
    #pragma unroll
    for(int w=0;w<8;w++){
        float qv = q[w];
        g_qcol[(b*8+w)*NS + t] = tf32r(qv);
        u32 hp = pkbf(0.f, qv);                 // low half = bf16(qv)
        float hf = __uint_as_float(hp<<16);
        u32 lp = pkbf(0.f, qv - hf);
        g_vhi[(b*8+w)*NS + t] = (unsigned short)(hp & 0xffffu);
        g_vlo[(b*8+w)*NS + t] = (unsigned short)(lp & 0xffffu);
    }
}

// ---------------------------------------------------------------------------
// Kernel 2: flash attention via warp mma.sync, double-buffered cp.async.
//   Warp owns 16 s-rows. Per 16-t subtile:
//     2x mma.m16n8k8.tf32 -> S ; 8x ex2 -> P ; 4x cvt -> P bf16 A-frag ;
//     2x mma.m16n8k16.bf16 (V hi + V lo, precomputed in feat).
//   Scores bounded => no online max. MUFU is the target wall (~57us).
// ---------------------------------------------------------------------------
__global__ void __launch_bounds__(128) attn_kernel()
{
    __shared__ __align__(16) float sk[2][8*KS];
    __shared__ __align__(16) u32   svh[2][8*VS];
    __shared__ __align__(16) u32   svl[2][8*VS];

    const int b    = blockIdx.y;
    const int tid  = threadIdx.x;
    const int warp = tid >> 5, lane = tid & 31;
    const int g    = lane >> 2, c = lane & 3;
    const int row0 = blockIdx.x*64 + warp*16;

    const float* qc = &g_qcol[b*8*NS];
    const unsigned short* vh = &g_vhi[b*8*NS];
    const unsigned short* vl = &g_vlo[b*8*NS];

    u32 skb  = (u32)__cvta_generic_to_shared(&sk[0][0]);
    u32 svhb = (u32)__cvta_generic_to_shared(&svh[0][0]);
    u32 svlb = (u32)__cvta_generic_to_shared(&svl[0][0]);

    // Q fragment (held whole kernel)
    const float* qr = &g_qrow[(b*NS+row0)*8];
    u32 qa[4];
    qa[0] = __float_as_uint(qr[ g   *8 + c  ]);
    qa[1] = __float_as_uint(qr[(g+8)*8 + c  ]);
    qa[2] = __float_as_uint(qr[ g   *8 + c+4]);
    qa[3] = __float_as_uint(qr[(g+8)*8 + c+4]);

    float num[4] = {0.f,0.f,0.f,0.f};
    float denl = 0.f, denh = 0.f;

    // chunk loader: 512 K-segs + 256 vhi-segs + 256 vlo-segs of 16B
    auto load_chunk = [&](int ch, int st){
        int t0 = ch*CHUNK;
        u32 kb = skb  + (u32)(st*8*KS)*4u;
        u32 hb = svhb + (u32)(st*8*VS)*4u;
        u32 lb = svlb + (u32)(st*8*VS)*4u;
        #pragma unroll
        for(int k=0;k<4;k++){
            int i = tid + k*128, row = i>>6, off = i&63;
            cpa16(kb + (u32)(row*KS+off*4)*4u, qc + row*NS + t0 + off*4);
        }
        #pragma unroll
        for(int k=0;k<2;k++){
            int i = tid + k*128, row = i>>5, off = i&31;
            cpa16(hb + (u32)(row*VS+off*4)*4u, vh + row*NS + t0 + off*8);
        }
        #pragma unroll
        for(int k=0;k<2;k++){
            int i = tid + k*128, row = i>>5, off = i&31;
            cpa16(lb + (u32)(row*VS+off*4)*4u, vl + row*NS + t0 + off*8);
        }
        cpa_commit();
    };

    load_chunk(0, 0);

    for(int ch=0; ch<NCH; ch++){
        int st = ch & 1;
        if(ch+1 < NCH) load_chunk(ch+1, (ch+1)&1);
        else           cpa_commit();           // empty group keeps wait count uniform
        cpa_wait1();                           // chunk ch resident
        __syncthreads();

        const float* K  = &sk[st][0];
        const u32*   VH = &svh[st][0];
        const u32*   VL = &svl[st][0];

        #pragma unroll 4
        for(int sub=0; sub<CHUNK/16; sub++){
            const int tb = sub*16;
            u32 kb00 = __float_as_uint(K[ c   *KS + tb + g    ]);
            u32 kb01 = __float_as_uint(K[(c+4)*KS + tb + g    ]);
            u32 kb10 = __float_as_uint(K[ c   *KS + tb + 8 + g]);
            u32 kb11 = __float_as_uint(K[(c+4)*KS + tb + 8 + g]);
            float dl[4], dr[4];
            mma_tf32(dl, qa, kb00, kb01);
            mma_tf32(dr, qa, kb10, kb11);
            dl[0]=ex2f(dl[0]); dl[1]=ex2f(dl[1]); dl[2]=ex2f(dl[2]); dl[3]=ex2f(dl[3]);
            dr[0]=ex2f(dr[0]); dr[1]=ex2f(dr[1]); dr[2]=ex2f(dr[2]); dr[3]=ex2f(dr[3]);
            denl += dl[0]+dl[1]+dr[0]+dr[1];
            denh += dl[2]+dl[3]+dr[2]+dr[3];
            u32 pa[4];
            pa[0]=pkbf(dl[1],dl[0]); pa[1]=pkbf(dl[3],dl[2]);
            pa[2]=pkbf(dr[1],dr[0]); pa[3]=pkbf(dr[3],dr[2]);
            // V fragments: row e=g, k pairs along t (precomputed bf16x2)
            int vi = g*VS + (tb>>1);
            u32 vh0 = VH[vi + c], vh1 = VH[vi + 4 + c];
            u32 vl0 = VL[vi + c], vl1 = VL[vi + 4 + c];
            mma_bf16(num, pa, vh0, vh1);
            mma_bf16(num, pa, vl0, vl1);
        }
        __syncthreads();
    }

    denl += __shfl_xor_sync(0xffffffffu, denl, 1);
    denl += __shfl_xor_sync(0xffffffffu, denl, 2);
    denh += __shfl_xor_sync(0xffffffffu, denh, 1);
    denh += __shfl_xor_sync(0xffffffffu, denh, 2);
    float invl = 1.0f/denl, invh = 1.0f/denh;

    float* o1 = &g_att[(b*NS + row0 + g    )*8 + 2*c];
    float* o2 = &g_att[(b*NS + row0 + 8 + g)*8 + 2*c];
    *(float2*)o1 = make_float2(num[0]*invl, num[1]*invl);
    *(float2*)o2 = make_float2(num[2]*invh, num[3]*invh);
}

// ---------------------------------------------------------------------------
// Kernel 3: swapaxes(1,2).reshape scramble + out @ W^T + b.
// ---------------------------------------------------------------------------
__global__ void epi_kernel(const float* __restrict__ W, const float* __restrict__ bias,
                           float* __restrict__ out)
{
    int idx = blockIdx.x*blockDim.x + threadIdx.x;   // b*NS + i
    int i  = idx & (NS-1);
    int b  = idx >> 12;
    int e  = i >> 9;
    int s0 = (i & 511) << 3;
    const float* gp = &g_att[(b*NS + s0)*8 + e];
    float y[8];
    #pragma unroll
    for(int j=0;j<8;j++) y[j] = gp[j*8];
    float r[8];
    #pragma unroll
    for(int ep=0;ep<8;ep++){
        float a = __ldg(&bias[ep]);
        #pragma unroll
        for(int j=0;j<8;j++) a = fmaf(y[j], __ldg(&W[ep*8+j]), a);
        r[ep]=a;
    }
    *(float4*)&out[idx*8]   = make_float4(r[0],r[1],r[2],r[3]);
    *(float4*)&out[idx*8+4] = make_float4(r[4],r[5],r[6],r[7]);
}

extern "C" void kernel_launch(void* const* d_in, const int* in_sizes, int n_in,
                              void* d_out, int out_size)
{
    const float* x     = (const float*)d_in[0];
    const float* theta = (const float*)d_in[1];
    const float* w     = (const float*)d_in[2];
    const float* bias  = (const float*)d_in[3];
    float* out = (float*)d_out;

    feat_kernel<<<NTOK/256, 256>>>(x, theta);
    dim3 g(NS/64, NB);
    attn_kernel<<<g, 128>>>();
    epi_kernel<<<NTOK/256, 256>>>(w, bias, out);
}

// round 7
// speedup vs baseline: 3.1599x; 1.0272x over previous
#include <cuda_runtime.h>

#define NB 16
#define NS 4096
#define NTOK (NB*NS)
#define CHUNK 256
#define KS 264             // padded f32 stride for K rows
#define VS 132             // padded u32 stride for V rows (bf16x2)
#define NCH (NS/CHUNK)

// scratch (device globals: no allocation allowed)
__device__ float g_qrow[NTOK*8];            // tf32(q*log2e/sqrt2) [b][s][w] (Q operand)
__device__ float g_qcol[NB*8*NS];           // tf32(q)             [b][w][t] (K operand)
__device__ unsigned short g_vhi[NB*8*NS];   // bf16 hi of q        [b][w][t] (V operand)
__device__ unsigned short g_vlo[NB*8*NS];   // bf16 lo residual

typedef unsigned int u32;

__device__ __forceinline__ float ex2f(float x){float r; asm("ex2.approx.ftz.f32 %0,%1;":"=f"(r):"f"(x)); return r;}
__device__ __forceinline__ float tf32r(float x){u32 r; asm("cvt.rna.tf32.f32 %0,%1;":"=r"(r):"f"(x)); return __uint_as_float(r);}
// pack: result.lo = lo, result.hi = hi
__device__ __forceinline__ u32 pkbf(float hi, float lo){u32 r; asm("cvt.rn.bf16x2.f32 %0,%1,%2;":"=r"(r):"f"(hi),"f"(lo)); return r;}
__device__ __forceinline__ void cpa16(u32 dst, const void* src){
    asm volatile("cp.async.cg.shared.global [%0], [%1], 16;"::"r"(dst),"l"(src));
}
__device__ __forceinline__ void cpa_commit(){ asm volatile("cp.async.commit_group;"); }
__device__ __forceinline__ void cpa_wait1(){ asm volatile("cp.async.wait_group 1;"); }

__device__ __forceinline__ void mma_tf32(float* d, const u32* a, u32 b0, u32 b1){
    asm volatile("mma.sync.aligned.m16n8k8.row.col.f32.tf32.tf32.f32 "
        "{%0,%1,%2,%3},{%4,%5,%6,%7},{%8,%9},{%10,%11,%12,%13};"
        : "=f"(d[0]),"=f"(d[1]),"=f"(d[2]),"=f"(d[3])
        : "r"(a[0]),"r"(a[1]),"r"(a[2]),"r"(a[3]), "r"(b0),"r"(b1),
          "f"(0.f),"f"(0.f),"f"(0.f),"f"(0.f));
}
__device__ __forceinline__ void mma_bf16(float* d, const u32* a, u32 b0, u32 b1){
    asm volatile("mma.sync.aligned.m16n8k16.row.col.f32.bf16.bf16.f32 "
        "{%0,%1,%2,%3},{%4,%5,%6,%7},{%8,%9},{%0,%1,%2,%3};"
        : "+f"(d[0]),"+f"(d[1]),"+f"(d[2]),"+f"(d[3])
        : "r"(a[0]),"r"(a[1]),"r"(a[2]),"r"(a[3]), "r"(b0),"r"(b1));
}

// ---------------------------------------------------------------------------
// Kernel 1: quantum features (prefix cosine products).
//   Emits: Q (tf32, pre-scaled), K (tf32), V as bf16 hi/lo split.
// ---------------------------------------------------------------------------
__global__ void feat_kernel(const float* __restrict__ x, const float* __restrict__ theta)
{
    int tok = blockIdx.x*blockDim.x + threadIdx.x;
    float th[8];
    #pragma unroll
    for(int w=0;w<8;w++) th[w] = __ldg(&theta[w]);
    float4 x0 = *(const float4*)&x[tok*8];
    float4 x1 = *(const float4*)&x[tok*8+4];
    float c[8];
    c[0]=__cosf(x0.x+th[0]); c[1]=__cosf(x0.y+th[1]); c[2]=__cosf(x0.z+th[2]); c[3]=__cosf(x0.w+th[3]);
    c[4]=__cosf(x1.x+th[4]); c[5]=__cosf(x1.y+th[5]); c[6]=__cosf(x1.z+th[6]); c[7]=__cosf(x1.w+th[7]);
    float q[8];
    float p = c[0];
    #pragma unroll
    for(int w=1;w<8;w++){ p *= c[w]; q[w] = p; }
    float s = c[1];
    #pragma unroll
    for(int w=2;w<8;w++) s *= c[w];
    q[0] = s;                                   // CNOT-ring inverse image
    const float SC = 1.02013946f;               // log2(e)/sqrt(2)
    float qs[8];
    #pragma unroll
    for(int w=0;w<8;w++) qs[w]=tf32r(q[w]*SC);
    *(float4*)&g_qrow[tok*8]   = make_float4(qs[0],qs[1],qs[2],qs[3]);
    *(float4*)&g_qrow[tok*8+4] = make_float4(qs[4],qs[5],qs[6],qs[7]);
    int b = tok >> 12, t = tok & (NS-1);
    #pragma unroll
    for(int w=0;w<8;w++){
        float qv = q[w];
        g_qcol[(b*8+w)*NS + t] = tf32r(qv);
        u32 hp = pkbf(0.f, qv);                 // low half = bf16(qv)
        float hf = __uint_as_float(hp<<16);
        u32 lp = pkbf(0.f, qv - hf);
        g_vhi[(b*8+w)*NS + t] = (unsigned short)(hp & 0xffffu);
        g_vlo[(b*8+w)*NS + t] = (unsigned short)(lp & 0xffffu);
    }
}

// ---------------------------------------------------------------------------
// Kernel 2: flash attention via warp mma.sync + FUSED epilogue.
//   Warp owns 16 s-rows. Per 16-t subtile:
//     2x mma.m16n8k8.tf32 -> S ; 8x ex2 -> P ; 4x cvt -> P bf16 A-frag ;
//     2x mma.m16n8k16.bf16 (V hi + V lo).
//   CTA owns 64 s-rows == exactly the att values needed by out rows
//   i = e*512 + 8*bx + m  -> stage 64x8 o-tile in smem, apply W,b in-CTA.
// ---------------------------------------------------------------------------
__global__ void __launch_bounds__(128) attn_kernel(const float* __restrict__ W,
                                                   const float* __restrict__ bias,
                                                   float* __restrict__ out)
{
    __shared__ __align__(16) float sk[2][8*KS];
    __shared__ __align__(16) u32   svh[2][8*VS];
    __shared__ __align__(16) u32   svl[2][8*VS];
    __shared__ float so[64*9];                   // o staging, stride 9 (conflict-free)

    const int b    = blockIdx.y;
    const int tid  = threadIdx.x;
    const int warp = tid >> 5, lane = tid & 31;
    const int g    = lane >> 2, c = lane & 3;
    const int row0 = blockIdx.x*64 + warp*16;

    const float* qc = &g_qcol[b*8*NS];
    const unsigned short* vh = &g_vhi[b*8*NS];
    const unsigned short* vl = &g_vlo[b*8*NS];

    u32 skb  = (u32)__cvta_generic_to_shared(&sk[0][0]);
    u32 svhb = (u32)__cvta_generic_to_shared(&svh[0][0]);
    u32 svlb = (u32)__cvta_generic_to_shared(&svl[0][0]);

    // Q fragment (held whole kernel)
    const float* qr = &g_qrow[(b*NS+row0)*8];
    u32 qa[4];
    qa[0] = __float_as_uint(qr[ g   *8 + c  ]);
    qa[1] = __float_as_uint(qr[(g+8)*8 + c  ]);
    qa[2] = __float_as_uint(qr[ g   *8 + c+4]);
    qa[3] = __float_as_uint(qr[(g+8)*8 + c+4]);

    float num[4] = {0.f,0.f,0.f,0.f};
    float denl = 0.f, denh = 0.f;

    auto load_chunk = [&](int ch, int st){
        int t0 = ch*CHUNK;
        u32 kb = skb  + (u32)(st*8*KS)*4u;
        u32 hb = svhb + (u32)(st*8*VS)*4u;
        u32 lb = svlb + (u32)(st*8*VS)*4u;
        #pragma unroll
        for(int k=0;k<4;k++){
            int i = tid + k*128, row = i>>6, off = i&63;
            cpa16(kb + (u32)(row*KS+off*4)*4u, qc + row*NS + t0 + off*4);
        }
        #pragma unroll
        for(int k=0;k<2;k++){
            int i = tid + k*128, row = i>>5, off = i&31;
            cpa16(hb + (u32)(row*VS+off*4)*4u, vh + row*NS + t0 + off*8);
        }
        #pragma unroll
        for(int k=0;k<2;k++){
            int i = tid + k*128, row = i>>5, off = i&31;
            cpa16(lb + (u32)(row*VS+off*4)*4u, vl + row*NS + t0 + off*8);
        }
        cpa_commit();
    };

    load_chunk(0, 0);

    for(int ch=0; ch<NCH; ch++){
        int st = ch & 1;
        if(ch+1 < NCH) load_chunk(ch+1, (ch+1)&1);
        else           cpa_commit();           // empty group keeps wait count uniform
        cpa_wait1();
        __syncthreads();

        const float* K  = &sk[st][0];
        const u32*   VH = &svh[st][0];
        const u32*   VL = &svl[st][0];

        #pragma unroll 4
        for(int sub=0; sub<CHUNK/16; sub++){
            const int tb = sub*16;
            u32 kb00 = __float_as_uint(K[ c   *KS + tb + g    ]);
            u32 kb01 = __float_as_uint(K[(c+4)*KS + tb + g    ]);
            u32 kb10 = __float_as_uint(K[ c   *KS + tb + 8 + g]);
            u32 kb11 = __float_as_uint(K[(c+4)*KS + tb + 8 + g]);
            float dl[4], dr[4];
            mma_tf32(dl, qa, kb00, kb01);
            mma_tf32(dr, qa, kb10, kb11);
            dl[0]=ex2f(dl[0]); dl[1]=ex2f(dl[1]); dl[2]=ex2f(dl[2]); dl[3]=ex2f(dl[3]);
            dr[0]=ex2f(dr[0]); dr[1]=ex2f(dr[1]); dr[2]=ex2f(dr[2]); dr[3]=ex2f(dr[3]);
            denl += dl[0]+dl[1]+dr[0]+dr[1];
            denh += dl[2]+dl[3]+dr[2]+dr[3];
            u32 pa[4];
            pa[0]=pkbf(dl[1],dl[0]); pa[1]=pkbf(dl[3],dl[2]);
            pa[2]=pkbf(dr[1],dr[0]); pa[3]=pkbf(dr[3],dr[2]);
            int vi = g*VS + (tb>>1);
            u32 vh0 = VH[vi + c], vh1 = VH[vi + 4 + c];
            u32 vl0 = VL[vi + c], vl1 = VL[vi + 4 + c];
            mma_bf16(num, pa, vh0, vh1);
            mma_bf16(num, pa, vl0, vl1);
        }
        __syncthreads();
    }

    denl += __shfl_xor_sync(0xffffffffu, denl, 1);
    denl += __shfl_xor_sync(0xffffffffu, denl, 2);
    denh += __shfl_xor_sync(0xffffffffu, denh, 1);
    denh += __shfl_xor_sync(0xffffffffu, denh, 2);
    float invl = 1.0f/denl, invh = 1.0f/denh;

    // stage normalized o tile: so[localRow][e], stride 9
    int lr = warp*16 + g;
    so[ lr   *9 + 2*c] = num[0]*invl;  so[ lr   *9 + 2*c+1] = num[1]*invl;
    so[(lr+8)*9 + 2*c] = num[2]*invh;  so[(lr+8)*9 + 2*c+1] = num[3]*invh;
    __syncthreads();

    // fused epilogue: out[b, e*512 + 8*bx + m, :] = bias + so[8m+j][e] . W[:,j]
    if(tid < 64){
        int e = tid >> 3, m = tid & 7;
        float y[8];
        #pragma unroll
        for(int j=0;j<8;j++) y[j] = so[(8*m+j)*9 + e];
        float r[8];
        #pragma unroll
        for(int ep=0;ep<8;ep++){
            float a = __ldg(&bias[ep]);
            #pragma unroll
            for(int j=0;j<8;j++) a = fmaf(y[j], __ldg(&W[ep*8+j]), a);
            r[ep]=a;
        }
        int i = e*512 + blockIdx.x*8 + m;
        float* op = &out[(b*NS + i)*8];
        *(float4*)op     = make_float4(r[0],r[1],r[2],r[3]);
        *(float4*)(op+4) = make_float4(r[4],r[5],r[6],r[7]);
    }
}

extern "C" void kernel_launch(void* const* d_in, const int* in_sizes, int n_in,
                              void* d_out, int out_size)
{
    const float* x     = (const float*)d_in[0];
    const float* theta = (const float*)d_in[1];
    const float* w     = (const float*)d_in[2];
    const float* bias  = (const float*)d_in[3];
    float* out = (float*)d_out;

    feat_kernel<<<NTOK/256, 256>>>(x, theta);
    dim3 g(NS/64, NB);
    attn_kernel<<<g, 128>>>(w, bias, out);
}